// round 1
// baseline (speedup 1.0000x reference)
#include <cuda_runtime.h>
#include <cstdint>

#define N_B 32
#define S_LEN 1024
#define HEADS 4
#define HD 32
#define EMB 128
#define BQ 32
#define TK 128
#define KPAD 36
#define SS 1032
#define SCALE 0.08838834764831845f   // 1/sqrt(128)

// Scratch (static device globals: allocation-free per harness rules)
__device__ float g_q[N_B*HEADS*S_LEN*HD];
__device__ float g_k[N_B*HEADS*S_LEN*HD];
__device__ float g_v[N_B*HEADS*S_LEN*HD];
__device__ float g_ctx[(size_t)N_B*S_LEN*EMB];

// ---- packed fp32x2 helpers (Blackwell FFMA2 via PTX) ----
__device__ __forceinline__ unsigned long long pack2(float lo, float hi){
    unsigned long long r;
    asm("mov.b64 %0, {%1, %2};" : "=l"(r) : "f"(lo), "f"(hi));
    return r;
}
__device__ __forceinline__ void fma2(unsigned long long &d, unsigned long long a, unsigned long long b){
    asm("fma.rn.f32x2 %0, %1, %2, %3;" : "=l"(d) : "l"(a), "l"(b), "l"(d));
}
__device__ __forceinline__ float2 unpack2(unsigned long long v){
    float2 f;
    asm("mov.b64 {%0, %1}, %2;" : "=f"(f.x), "=f"(f.y) : "l"(v));
    return f;
}

// FMA-pipe exp (avoids MUFU throughput wall: 134M exps). x <= 0 expected.
__device__ __forceinline__ float fexp(float x){
    x = fmaxf(x, -80.0f);
    float t = x * 1.4426950408889634f;
    float fn = rintf(t);
    float f = t - fn;
    float p = 1.3333558146e-3f;
    p = fmaf(p, f, 9.6181291076e-3f);
    p = fmaf(p, f, 5.5504108664e-2f);
    p = fmaf(p, f, 2.4022650696e-1f);
    p = fmaf(p, f, 6.9314718056e-1f);
    p = fmaf(p, f, 1.0f);
    float s = __int_as_float(((int)fn + 127) << 23);
    return p * s;
}

// ============================================================
// Kernel 1: per-head projections q,k,v  (x @ W.T per head)
// block = 128 threads, 16 (n,s) rows per block
// ============================================================
__global__ __launch_bounds__(128) void proj_kernel(
    const float* __restrict__ vin, const float* __restrict__ kin,
    const float* __restrict__ qin,
    const float* __restrict__ Wv, const float* __restrict__ Wk,
    const float* __restrict__ Wq)
{
    __shared__ float sW[3][32*33];
    __shared__ float srow[3][16*128];
    int t = threadIdx.x;
    for (int i = t; i < 1024; i += 128){
        int d = i >> 5, e = i & 31;
        sW[0][d*33+e] = __ldg(Wv + i);
        sW[1][d*33+e] = __ldg(Wk + i);
        sW[2][d*33+e] = __ldg(Wq + i);
    }
    int row0 = blockIdx.x * 16;
    const float4* s0 = (const float4*)(vin + (size_t)row0*128);
    const float4* s1 = (const float4*)(kin + (size_t)row0*128);
    const float4* s2 = (const float4*)(qin + (size_t)row0*128);
    #pragma unroll
    for (int i = 0; i < 4; i++){
        int idx = t + i*128;
        ((float4*)srow[0])[idx] = __ldg(s0 + idx);
        ((float4*)srow[1])[idx] = __ldg(s1 + idx);
        ((float4*)srow[2])[idx] = __ldg(s2 + idx);
    }
    __syncthreads();
    int h = t >> 5, d = t & 31;
    int n = row0 >> 10;
    int sbase = row0 & 1023;
    for (int i = 0; i < 16; i++){
        float av = 0.f, ak = 0.f, aq = 0.f;
        const float* rv = &srow[0][i*128 + h*32];
        const float* rk = &srow[1][i*128 + h*32];
        const float* rq = &srow[2][i*128 + h*32];
        #pragma unroll
        for (int e = 0; e < 32; e++){
            av = fmaf(sW[0][d*33+e], rv[e], av);
            ak = fmaf(sW[1][d*33+e], rk[e], ak);
            aq = fmaf(sW[2][d*33+e], rq[e], aq);
        }
        size_t o = ((size_t)(n*HEADS + h)*S_LEN + sbase + i)*HD + d;
        g_v[o] = av; g_k[o] = ak; g_q[o] = aq;
    }
}

// ============================================================
// Kernel 2: fused QK^T -> mask -> softmax -> weights-out -> PV
// one CTA per (n, h, 32 q-rows); 256 threads
// thread t: row r = t>>3, lane-group c = t&7
// ============================================================
__global__ __launch_bounds__(256) void attn_kernel(
    const int* __restrict__ mask, float* __restrict__ attw)
{
    extern __shared__ float sm[];
    float* ssc = sm;                  // BQ * SS scores/weights
    float* skv = sm + BQ*SS;          // TK * KPAD k/v tile
    int bid = blockIdx.x;
    int qb = bid & 31;
    int h  = (bid >> 5) & 3;
    int n  = bid >> 7;
    int t = threadIdx.x;
    int r = t >> 3;
    int c = t & 7;
    int q = qb*BQ + r;
    size_t headoff = (size_t)(n*HEADS + h)*S_LEN*HD;

    // Q row into packed registers (8 threads/row -> L1 broadcast)
    const float* qrow = g_q + headoff + (size_t)q*HD;
    unsigned long long qq[16];
    #pragma unroll
    for (int i = 0; i < 16; i++){
        float2 v = __ldg(((const float2*)qrow) + i);
        qq[i] = pack2(v.x, v.y);
    }

    // ---- Phase 1: scores = (Q K^T) * scale ----
    const float* kbase = g_k + headoff;
    for (int kt = 0; kt < S_LEN/TK; kt++){
        __syncthreads();
        const float4* srcp = (const float4*)(kbase + (size_t)kt*TK*HD);
        #pragma unroll
        for (int i = 0; i < 4; i++){
            int idx = t + i*256;
            int kr = idx >> 3;
            int ke = (idx & 7) << 2;
            *(float4*)&skv[kr*KPAD + ke] = __ldg(srcp + idx);
        }
        __syncthreads();
        #pragma unroll 4
        for (int j = 0; j < 16; j++){
            int k = c + (j << 3);                 // k-interleave: bank-friendly
            const float* krow = &skv[k*KPAD];
            unsigned long long a = 0ull, b = 0ull;
            #pragma unroll
            for (int e = 0; e < 16; e += 2){
                ulonglong2 kk = *(const ulonglong2*)&krow[e*2];
                fma2(a, qq[e],   kk.x);
                fma2(b, qq[e+1], kk.y);
            }
            float2 fa = unpack2(a), fb = unpack2(b);
            ssc[r*SS + kt*TK + k] = (fa.x + fa.y + fb.x + fb.y) * SCALE;
        }
    }

    // ---- Phase 2: mask + softmax (row handled by its own 8 threads; same warp) ----
    const int* mrow = mask + (size_t)n*S_LEN*S_LEN + (size_t)q*S_LEN;
    float mx = -3e38f;
    for (int j = 0; j < 128; j++){
        int k = c + (j << 3);
        float s = ssc[r*SS + k];
        if (__ldg(mrow + k) == 0){ s = -1e30f; ssc[r*SS + k] = s; }
        mx = fmaxf(mx, s);
    }
    mx = fmaxf(mx, __shfl_xor_sync(0xffffffffu, mx, 1));
    mx = fmaxf(mx, __shfl_xor_sync(0xffffffffu, mx, 2));
    mx = fmaxf(mx, __shfl_xor_sync(0xffffffffu, mx, 4));
    float sum = 0.f;
    for (int j = 0; j < 128; j++){
        int k = c + (j << 3);
        float w = fexp(ssc[r*SS + k] - mx);
        ssc[r*SS + k] = w;
        sum += w;
    }
    sum += __shfl_xor_sync(0xffffffffu, sum, 1);
    sum += __shfl_xor_sync(0xffffffffu, sum, 2);
    sum += __shfl_xor_sync(0xffffffffu, sum, 4);
    float inv = 1.0f / sum;
    float* wout = attw + ((size_t)(n*HEADS + h)*S_LEN + q)*S_LEN;
    for (int j = 0; j < 128; j++){
        int k = c + (j << 3);
        float w = ssc[r*SS + k] * inv;
        ssc[r*SS + k] = w;
        wout[k] = w;
    }
    __syncwarp();

    // ---- Phase 3: ctx = W @ V ----
    const float* vbase = g_v + headoff;
    int d0 = c << 2;
    unsigned long long a00=0ull, a01=0ull, a10=0ull, a11=0ull;
    for (int kt = 0; kt < S_LEN/TK; kt++){
        __syncthreads();
        const float4* srcp = (const float4*)(vbase + (size_t)kt*TK*HD);
        #pragma unroll
        for (int i = 0; i < 4; i++){
            int idx = t + i*256;
            int kr = idx >> 3;
            int ke = (idx & 7) << 2;
            *(float4*)&skv[kr*KPAD + ke] = __ldg(srcp + idx);
        }
        __syncthreads();
        #pragma unroll 2
        for (int k4 = 0; k4 < TK; k4 += 4){
            float4 w4 = *(const float4*)&ssc[r*SS + kt*TK + k4];
            ulonglong2 v0 = *(const ulonglong2*)&skv[(k4+0)*KPAD + d0];
            ulonglong2 v1 = *(const ulonglong2*)&skv[(k4+1)*KPAD + d0];
            ulonglong2 v2 = *(const ulonglong2*)&skv[(k4+2)*KPAD + d0];
            ulonglong2 v3 = *(const ulonglong2*)&skv[(k4+3)*KPAD + d0];
            unsigned long long w0 = pack2(w4.x, w4.x);
            unsigned long long w1 = pack2(w4.y, w4.y);
            unsigned long long w2 = pack2(w4.z, w4.z);
            unsigned long long w3 = pack2(w4.w, w4.w);
            fma2(a00, w0, v0.x); fma2(a01, w0, v0.y);
            fma2(a10, w1, v1.x); fma2(a11, w1, v1.y);
            fma2(a00, w2, v2.x); fma2(a01, w2, v2.y);
            fma2(a10, w3, v3.x); fma2(a11, w3, v3.y);
        }
    }
    float2 p0 = unpack2(a00), p1 = unpack2(a01);
    float2 r0 = unpack2(a10), r1 = unpack2(a11);
    float4 o;
    o.x = p0.x + r0.x; o.y = p0.y + r0.y;
    o.z = p1.x + r1.x; o.w = p1.y + r1.y;
    float* cdst = g_ctx + ((size_t)(n*S_LEN + q))*EMB + h*HD + d0;
    *(float4*)cdst = o;
}

// ============================================================
// Kernel 3: out = ctx @ Wo.T + bo   (Wo transposed in smem)
// ============================================================
__global__ __launch_bounds__(128) void out_kernel(
    const float* __restrict__ Wo, const float* __restrict__ bo,
    float* __restrict__ out)
{
    extern __shared__ float sm[];
    float* sWoT = sm;            // 128*128 (transposed: [e][o])
    float* srow = sm + 16384;    // 32*128
    int t = threadIdx.x;
    #pragma unroll
    for (int e = 0; e < 128; e += 4){
        float4 w4 = __ldg((const float4*)(Wo + (size_t)t*128 + e));
        sWoT[(e+0)*128 + t] = w4.x;
        sWoT[(e+1)*128 + t] = w4.y;
        sWoT[(e+2)*128 + t] = w4.z;
        sWoT[(e+3)*128 + t] = w4.w;
    }
    int row0 = blockIdx.x * 32;
    const float4* src = (const float4*)(g_ctx + (size_t)row0*EMB);
    #pragma unroll
    for (int i = 0; i < 8; i++){
        ((float4*)srow)[t + i*128] = src[t + i*128];
    }
    __syncthreads();
    float b = __ldg(bo + t);
    for (int i = 0; i < 32; i++){
        float acc = b;
        const float* rr = &srow[i*128];
        #pragma unroll 16
        for (int e = 0; e < 128; e++){
            acc = fmaf(sWoT[e*128 + t], rr[e], acc);
        }
        out[(size_t)(row0 + i)*EMB + t] = acc;
    }
}

// ============================================================
extern "C" void kernel_launch(void* const* d_in, const int* in_sizes, int n_in,
                              void* d_out, int out_size)
{
    const float* values = (const float*)d_in[0];
    const float* keys   = (const float*)d_in[1];
    const float* query  = (const float*)d_in[2];
    const int*   mask   = (const int*)d_in[3];
    const float* Wv     = (const float*)d_in[4];
    const float* Wk     = (const float*)d_in[5];
    const float* Wq     = (const float*)d_in[6];
    const float* Wo     = (const float*)d_in[7];
    const float* bo     = (const float*)d_in[8];

    float* out  = (float*)d_out;
    float* attw = out + (size_t)N_B*S_LEN*EMB;   // tuple order: (out, attention_weights)

    cudaFuncSetAttribute(attn_kernel, cudaFuncAttributeMaxDynamicSharedMemorySize, (BQ*SS + TK*KPAD)*4);
    cudaFuncSetAttribute(out_kernel,  cudaFuncAttributeMaxDynamicSharedMemorySize, (16384 + 4096)*4);

    proj_kernel<<<(N_B*S_LEN)/16, 128>>>(values, keys, query, Wv, Wk, Wq);
    attn_kernel<<<N_B*HEADS*(S_LEN/BQ), 256, (BQ*SS + TK*KPAD)*4>>>(mask, attw);
    out_kernel<<<(N_B*S_LEN)/32, 128, (16384 + 4096)*4>>>(Wo, bo, out);
}

// round 5
// speedup vs baseline: 2.8344x; 2.8344x over previous
#include <cuda_runtime.h>
#include <cuda_bf16.h>
#include <cstdint>

#define N_B 32
#define S_LEN 1024
#define HEADS 4
#define HD 32
#define EMB 128
#define LOG2E 1.4426950408889634f
#define SCALE 0.08838834764831845f      // 1/sqrt(128)
#define QSCALE (SCALE * LOG2E)

// ---------------- device scratch (no allocs allowed) ----------------
__device__ __nv_bfloat16 g_qhi[N_B*HEADS*S_LEN*HD];
__device__ __nv_bfloat16 g_qlo[N_B*HEADS*S_LEN*HD];
__device__ __nv_bfloat16 g_khi[N_B*HEADS*S_LEN*HD];
__device__ __nv_bfloat16 g_klo[N_B*HEADS*S_LEN*HD];
__device__ __nv_bfloat16 g_vhi[N_B*HEADS*S_LEN*HD];
__device__ __nv_bfloat16 g_vlo[N_B*HEADS*S_LEN*HD];
__device__ uint32_t g_mbits[(size_t)N_B*S_LEN*(S_LEN/32)];
__device__ float g_ctx[(size_t)N_B*S_LEN*EMB];

// ---------------- helpers ----------------
__device__ __forceinline__ uint32_t smem_u32(const void* p){
    uint32_t a;
    asm("{ .reg .u64 t; cvta.to.shared.u64 t, %1; cvt.u32.u64 %0, t; }" : "=r"(a) : "l"(p));
    return a;
}
__device__ __forceinline__ float ex2f(float x){
    float y; asm("ex2.approx.f32 %0, %1;" : "=f"(y) : "f"(x)); return y;
}
// pack two f32 -> bf16x2 (lo -> low half, hi -> high half)
__device__ __forceinline__ uint32_t packbf(float lo, float hi){
    uint32_t d; asm("cvt.rn.bf16x2.f32 %0, %1, %2;" : "=r"(d) : "f"(hi), "f"(lo)); return d;
}
__device__ __forceinline__ void ldsm_x4(uint32_t* r, uint32_t addr){
    asm volatile("ldmatrix.sync.aligned.m8n8.x4.shared.b16 {%0,%1,%2,%3}, [%4];"
        : "=r"(r[0]), "=r"(r[1]), "=r"(r[2]), "=r"(r[3]) : "r"(addr));
}
__device__ __forceinline__ void ldsm_x4t(uint32_t* r, uint32_t addr){
    asm volatile("ldmatrix.sync.aligned.m8n8.x4.trans.shared.b16 {%0,%1,%2,%3}, [%4];"
        : "=r"(r[0]), "=r"(r[1]), "=r"(r[2]), "=r"(r[3]) : "r"(addr));
}
__device__ __forceinline__ void mma16816(float* c, const uint32_t* a, const uint32_t* b){
    asm volatile("mma.sync.aligned.m16n8k16.row.col.f32.bf16.bf16.f32 "
        "{%0,%1,%2,%3}, {%4,%5,%6,%7}, {%8,%9}, {%0,%1,%2,%3};"
        : "+f"(c[0]), "+f"(c[1]), "+f"(c[2]), "+f"(c[3])
        : "r"(a[0]), "r"(a[1]), "r"(a[2]), "r"(a[3]), "r"(b[0]), "r"(b[1]));
}

// ---------------- smem layout for attn (byte offsets; row stride 80B) ----------------
#define RS 80
#define SM_QHI 0
#define SM_QLO 10240
#define SM_KHI 20480
#define SM_KLO 30720
#define SM_VHI 40960
#define SM_VLO 51200
#define SM_MB  61440
#define SM_TOTAL 64000

// ============================================================
// Kernel 0: bit-pack the mask (134MB int32 -> 4MB bits)
// ============================================================
__global__ __launch_bounds__(256) void maskbits_kernel(const int* __restrict__ mask)
{
    size_t w = (size_t)blockIdx.x * 256 + threadIdx.x;     // 1M words
    const int4* p = (const int4*)(mask + w * 32);
    uint32_t b = 0;
    #pragma unroll
    for (int i = 0; i < 8; i++){
        int4 v = __ldg(p + i);
        b |= (v.x != 0 ? 1u : 0u) << (i*4 + 0);
        b |= (v.y != 0 ? 1u : 0u) << (i*4 + 1);
        b |= (v.z != 0 ? 1u : 0u) << (i*4 + 2);
        b |= (v.w != 0 ? 1u : 0u) << (i*4 + 3);
    }
    g_mbits[w] = b;
}

// ============================================================
// Kernel 1: projections -> bf16 hi/lo; Q pre-scaled by log2e/sqrt(128)
// ============================================================
__global__ __launch_bounds__(128) void proj_kernel(
    const float* __restrict__ vin, const float* __restrict__ kin,
    const float* __restrict__ qin,
    const float* __restrict__ Wv, const float* __restrict__ Wk,
    const float* __restrict__ Wq)
{
    __shared__ float sW[3][32*33];
    __shared__ float srow[3][16*128];
    int t = threadIdx.x;
    for (int i = t; i < 1024; i += 128){
        int d = i >> 5, e = i & 31;
        sW[0][d*33+e] = __ldg(Wv + i);
        sW[1][d*33+e] = __ldg(Wk + i);
        sW[2][d*33+e] = __ldg(Wq + i);
    }
    int row0 = blockIdx.x * 16;
    const float4* s0 = (const float4*)(vin + (size_t)row0*128);
    const float4* s1 = (const float4*)(kin + (size_t)row0*128);
    const float4* s2 = (const float4*)(qin + (size_t)row0*128);
    #pragma unroll
    for (int i = 0; i < 4; i++){
        int idx = t + i*128;
        ((float4*)srow[0])[idx] = __ldg(s0 + idx);
        ((float4*)srow[1])[idx] = __ldg(s1 + idx);
        ((float4*)srow[2])[idx] = __ldg(s2 + idx);
    }
    __syncthreads();
    int h = t >> 5, d = t & 31;
    int n = row0 >> 10;
    int sbase = row0 & 1023;
    for (int i = 0; i < 16; i++){
        float av = 0.f, ak = 0.f, aq = 0.f;
        const float* rv = &srow[0][i*128 + h*32];
        const float* rk = &srow[1][i*128 + h*32];
        const float* rq = &srow[2][i*128 + h*32];
        #pragma unroll
        for (int e = 0; e < 32; e++){
            av = fmaf(sW[0][d*33+e], rv[e], av);
            ak = fmaf(sW[1][d*33+e], rk[e], ak);
            aq = fmaf(sW[2][d*33+e], rq[e], aq);
        }
        float qs = aq * QSCALE;
        __nv_bfloat16 qh = __float2bfloat16(qs);
        __nv_bfloat16 ql = __float2bfloat16(qs - __bfloat162float(qh));
        __nv_bfloat16 kh = __float2bfloat16(ak);
        __nv_bfloat16 kl = __float2bfloat16(ak - __bfloat162float(kh));
        __nv_bfloat16 vh = __float2bfloat16(av);
        __nv_bfloat16 vl = __float2bfloat16(av - __bfloat162float(vh));
        size_t o = ((size_t)(n*HEADS + h)*S_LEN + sbase + i)*HD + d;
        g_qhi[o] = qh; g_qlo[o] = ql;
        g_khi[o] = kh; g_klo[o] = kl;
        g_vhi[o] = vh; g_vlo[o] = vl;
    }
}

// ============================================================
// Kernel 2: fused HMMA attention. CTA = (n,h,128 q-rows), 256 thr, 8 warps x m16.
// ============================================================
__global__ __launch_bounds__(256, 1) void attn_kernel(float* __restrict__ attw)
{
    extern __shared__ char sm[];
    uint32_t smb = smem_u32(sm);
    int t = threadIdx.x;
    int l = t & 31, w = t >> 5;
    int bid = blockIdx.x;
    int h = bid & 3, qt = (bid >> 2) & 7, n = bid >> 5;   // h fastest: K/V/mask L2 reuse
    int nh = n*HEADS + h;
    size_t hoff = (size_t)nh * S_LEN * HD;
    int qrow0 = qt * 128;
    int wm0 = w * 16;
    int g = l >> 2, u = l & 3;

    // ---- stage Q tile (hi/lo) into smem, then load persistent A-frags
    #pragma unroll
    for (int i = 0; i < 2; i++){
        int idx = t + i*256;                  // 512 chunks of 16B
        int row = idx >> 2, part = idx & 3;
        int so = row*RS + part*16;
        const char* qh_src = (const char*)(g_qhi + hoff + (size_t)(qrow0+row)*HD) + part*16;
        const char* ql_src = (const char*)(g_qlo + hoff + (size_t)(qrow0+row)*HD) + part*16;
        *(uint4*)(sm + SM_QHI + so) = *(const uint4*)qh_src;
        *(uint4*)(sm + SM_QLO + so) = *(const uint4*)ql_src;
    }
    __syncthreads();
    uint32_t qh0[4], qh1[4], ql0[4], ql1[4];
    {
        uint32_t rowb = (uint32_t)((wm0 + ((l & 8) ? 8 : 0) + (l & 7))*RS + ((l & 16) ? 16 : 0));
        ldsm_x4(qh0, smb + SM_QHI + rowb);        // k-dims 0-15
        ldsm_x4(qh1, smb + SM_QHI + rowb + 32);   // k-dims 16-31
        ldsm_x4(ql0, smb + SM_QLO + rowb);
        ldsm_x4(ql1, smb + SM_QLO + rowb + 32);
    }

    float pv[4][4];
    #pragma unroll
    for (int i = 0; i < 4; i++){ pv[i][0]=0.f; pv[i][1]=0.f; pv[i][2]=0.f; pv[i][3]=0.f; }
    float l_r = 0.f, l_r8 = 0.f, inv_r = 0.f, inv_r8 = 0.f;

    float* wbase = attw + ((size_t)nh * S_LEN + qrow0) * S_LEN;
    const uint32_t* mb = (const uint32_t*)(sm + SM_MB);

    for (int sweep = 0; sweep < 2; sweep++){
        for (int kt = 0; kt < 8; kt++){
            __syncthreads();
            // ---- cooperative tile loads: K hi/lo (always), V hi/lo (sweep 0), mask bits
            {
                const char* kh_src = (const char*)(g_khi + hoff + (size_t)kt*128*HD);
                const char* kl_src = (const char*)(g_klo + hoff + (size_t)kt*128*HD);
                const char* vh_src = (const char*)(g_vhi + hoff + (size_t)kt*128*HD);
                const char* vl_src = (const char*)(g_vlo + hoff + (size_t)kt*128*HD);
                #pragma unroll
                for (int i = 0; i < 2; i++){
                    int idx = t + i*256;
                    int row = idx >> 2, part = idx & 3;
                    int go = row*64 + part*16;
                    int so = row*RS + part*16;
                    *(uint4*)(sm + SM_KHI + so) = *(const uint4*)(kh_src + go);
                    *(uint4*)(sm + SM_KLO + so) = *(const uint4*)(kl_src + go);
                    if (sweep == 0){
                        *(uint4*)(sm + SM_VHI + so) = *(const uint4*)(vh_src + go);
                        *(uint4*)(sm + SM_VLO + so) = *(const uint4*)(vl_src + go);
                    }
                }
                #pragma unroll
                for (int i = 0; i < 2; i++){
                    int idx = t + i*256;
                    int row = idx >> 2, j = idx & 3;
                    ((uint32_t*)(sm + SM_MB))[row*5 + j] =
                        g_mbits[((size_t)n*S_LEN + qrow0 + row)*32 + kt*4 + j];
                }
            }
            __syncthreads();

            // ---- QK^T: 16 n-tiles (8 keys each), 3-term hi/lo compensation
            float qk[16][4];
            #pragma unroll
            for (int i = 0; i < 16; i++){ qk[i][0]=0.f; qk[i][1]=0.f; qk[i][2]=0.f; qk[i][3]=0.f; }
            #pragma unroll
            for (int np = 0; np < 8; np++){
                uint32_t bh0[4], bh1[4], bl0[4], bl1[4];
                uint32_t rb = (uint32_t)((np*16 + ((l & 16) ? 8 : 0) + (l & 7))*RS + ((l & 8) ? 16 : 0));
                ldsm_x4(bh0, smb + SM_KHI + rb);
                ldsm_x4(bh1, smb + SM_KHI + rb + 32);
                ldsm_x4(bl0, smb + SM_KLO + rb);
                ldsm_x4(bl1, smb + SM_KLO + rb + 32);
                mma16816(qk[2*np],   qh0, bh0);     mma16816(qk[2*np+1], qh0, bh0+2);
                mma16816(qk[2*np],   qh1, bh1);     mma16816(qk[2*np+1], qh1, bh1+2);
                mma16816(qk[2*np],   qh0, bl0);     mma16816(qk[2*np+1], qh0, bl0+2);
                mma16816(qk[2*np],   qh1, bl1);     mma16816(qk[2*np+1], qh1, bl1+2);
                mma16816(qk[2*np],   ql0, bh0);     mma16816(qk[2*np+1], ql0, bh0+2);
                mma16816(qk[2*np],   ql1, bh1);     mma16816(qk[2*np+1], ql1, bh1+2);
            }

            // ---- mask words for this thread's two rows
            uint32_t wr[4], wr8[4];
            #pragma unroll
            for (int j = 0; j < 4; j++){
                wr[j]  = mb[g*5 + j];
                wr8[j] = mb[(g+8)*5 + j];
            }

            if (sweep == 0){
                // exp (base-2, pre-scaled), mask, row-sums, pack to bf16 hi/lo A-frags
                uint32_t ehi[32], elo[32];
                #pragma unroll
                for (int nt = 0; nt < 16; nt++){
                    int wj = nt >> 2;
                    int sh = (nt & 3)*8 + u*2;
                    float e0 = ((wr[wj]  >> sh)     & 1) ? ex2f(qk[nt][0]) : 0.f;
                    float e1 = ((wr[wj]  >> (sh+1)) & 1) ? ex2f(qk[nt][1]) : 0.f;
                    float e2 = ((wr8[wj] >> sh)     & 1) ? ex2f(qk[nt][2]) : 0.f;
                    float e3 = ((wr8[wj] >> (sh+1)) & 1) ? ex2f(qk[nt][3]) : 0.f;
                    l_r  += e0 + e1;
                    l_r8 += e2 + e3;
                    uint32_t p0 = packbf(e0, e1);
                    uint32_t p1 = packbf(e2, e3);
                    ehi[2*nt]   = p0;
                    ehi[2*nt+1] = p1;
                    float r0 = e0 - __uint_as_float(p0 << 16);
                    float r1 = e1 - __uint_as_float(p0 & 0xffff0000u);
                    float r2 = e2 - __uint_as_float(p1 << 16);
                    float r3 = e3 - __uint_as_float(p1 & 0xffff0000u);
                    elo[2*nt]   = packbf(r0, r1);
                    elo[2*nt+1] = packbf(r2, r3);
                }
                // ---- PV: ctx += P * V  (A from regs, B via ldmatrix.trans)
                #pragma unroll
                for (int kc = 0; kc < 8; kc++){
                    uint32_t vh0[4], vh1[4], vl0[4], vl1[4];
                    uint32_t rb = (uint32_t)((kc*16 + ((l & 8) ? 8 : 0) + (l & 7))*RS + ((l & 16) ? 16 : 0));
                    ldsm_x4t(vh0, smb + SM_VHI + rb);
                    ldsm_x4t(vh1, smb + SM_VHI + rb + 32);
                    ldsm_x4t(vl0, smb + SM_VLO + rb);
                    ldsm_x4t(vl1, smb + SM_VLO + rb + 32);
                    const uint32_t* ah = &ehi[4*kc];
                    const uint32_t* al = &elo[4*kc];
                    mma16816(pv[0], ah, vh0);   mma16816(pv[1], ah, vh0+2);
                    mma16816(pv[2], ah, vh1);   mma16816(pv[3], ah, vh1+2);
                    mma16816(pv[0], ah, vl0);   mma16816(pv[1], ah, vl0+2);
                    mma16816(pv[2], ah, vl1);   mma16816(pv[3], ah, vl1+2);
                    mma16816(pv[0], al, vh0);   mma16816(pv[1], al, vh0+2);
                    mma16816(pv[2], al, vh1);   mma16816(pv[3], al, vh1+2);
                }
            } else {
                // sweep 2: identical scores -> normalized weights out
                float* wr0p = wbase + (size_t)(wm0 + g)*S_LEN     + kt*128 + u*2;
                float* wr8p = wbase + (size_t)(wm0 + g + 8)*S_LEN + kt*128 + u*2;
                #pragma unroll
                for (int nt = 0; nt < 16; nt++){
                    int wj = nt >> 2;
                    int sh = (nt & 3)*8 + u*2;
                    float e0 = ((wr[wj]  >> sh)     & 1) ? ex2f(qk[nt][0]) : 0.f;
                    float e1 = ((wr[wj]  >> (sh+1)) & 1) ? ex2f(qk[nt][1]) : 0.f;
                    float e2 = ((wr8[wj] >> sh)     & 1) ? ex2f(qk[nt][2]) : 0.f;
                    float e3 = ((wr8[wj] >> (sh+1)) & 1) ? ex2f(qk[nt][3]) : 0.f;
                    float2 o0; o0.x = e0*inv_r;  o0.y = e1*inv_r;
                    float2 o1; o1.x = e2*inv_r8; o1.y = e3*inv_r8;
                    *(float2*)(wr0p + nt*8) = o0;
                    *(float2*)(wr8p + nt*8) = o1;
                }
            }
        }
        if (sweep == 0){
            l_r  += __shfl_xor_sync(0xffffffffu, l_r, 1);
            l_r  += __shfl_xor_sync(0xffffffffu, l_r, 2);
            l_r8 += __shfl_xor_sync(0xffffffffu, l_r8, 1);
            l_r8 += __shfl_xor_sync(0xffffffffu, l_r8, 2);
            inv_r  = 1.0f / l_r;
            inv_r8 = 1.0f / l_r8;
            // ---- write ctx (normalized)
            float* c0p = g_ctx + ((size_t)(n*S_LEN + qrow0 + wm0 + g))*EMB     + h*HD + u*2;
            float* c8p = g_ctx + ((size_t)(n*S_LEN + qrow0 + wm0 + g + 8))*EMB + h*HD + u*2;
            #pragma unroll
            for (int nt = 0; nt < 4; nt++){
                float2 o0; o0.x = pv[nt][0]*inv_r;  o0.y = pv[nt][1]*inv_r;
                float2 o1; o1.x = pv[nt][2]*inv_r8; o1.y = pv[nt][3]*inv_r8;
                *(float2*)(c0p + nt*8) = o0;
                *(float2*)(c8p + nt*8) = o1;
            }
        }
    }
}

// ============================================================
// Kernel 3: out = ctx @ Wo.T + bo
// ============================================================
__global__ __launch_bounds__(128) void out_kernel(
    const float* __restrict__ Wo, const float* __restrict__ bo,
    float* __restrict__ out)
{
    extern __shared__ float smf[];
    float* sWoT = smf;            // 128*128 transposed
    float* srow = smf + 16384;    // 32*128
    int t = threadIdx.x;
    #pragma unroll
    for (int e = 0; e < 128; e += 4){
        float4 w4 = __ldg((const float4*)(Wo + (size_t)t*128 + e));
        sWoT[(e+0)*128 + t] = w4.x;
        sWoT[(e+1)*128 + t] = w4.y;
        sWoT[(e+2)*128 + t] = w4.z;
        sWoT[(e+3)*128 + t] = w4.w;
    }
    int row0 = blockIdx.x * 32;
    const float4* src = (const float4*)(g_ctx + (size_t)row0*EMB);
    #pragma unroll
    for (int i = 0; i < 8; i++)
        ((float4*)srow)[t + i*128] = src[t + i*128];
    __syncthreads();
    float b = __ldg(bo + t);
    for (int i = 0; i < 32; i++){
        float acc = b;
        const float* rr = &srow[i*128];
        #pragma unroll 16
        for (int e = 0; e < 128; e++)
            acc = fmaf(sWoT[e*128 + t], rr[e], acc);
        out[(size_t)(row0 + i)*EMB + t] = acc;
    }
}

// ============================================================
extern "C" void kernel_launch(void* const* d_in, const int* in_sizes, int n_in,
                              void* d_out, int out_size)
{
    const float* values = (const float*)d_in[0];
    const float* keys   = (const float*)d_in[1];
    const float* query  = (const float*)d_in[2];
    const int*   mask   = (const int*)d_in[3];
    const float* Wv     = (const float*)d_in[4];
    const float* Wk     = (const float*)d_in[5];
    const float* Wq     = (const float*)d_in[6];
    const float* Wo     = (const float*)d_in[7];
    const float* bo     = (const float*)d_in[8];

    float* out  = (float*)d_out;
    float* attw = out + (size_t)N_B*S_LEN*EMB;   // tuple order: (out, attention_weights)

    cudaFuncSetAttribute(attn_kernel, cudaFuncAttributeMaxDynamicSharedMemorySize, SM_TOTAL);
    cudaFuncSetAttribute(out_kernel,  cudaFuncAttributeMaxDynamicSharedMemorySize, (16384 + 4096)*4);

    maskbits_kernel<<<(N_B*S_LEN*(S_LEN/32))/256, 256>>>(mask);
    proj_kernel<<<(N_B*S_LEN)/16, 128>>>(values, keys, query, Wv, Wk, Wq);
    attn_kernel<<<N_B*HEADS*(S_LEN/128), 256, SM_TOTAL>>>(attw);
    out_kernel<<<(N_B*S_LEN)/32, 128, (16384 + 4096)*4>>>(Wo, bo, out);
}

// round 10
// speedup vs baseline: 4.7417x; 1.6729x over previous
#include <cuda_runtime.h>
#include <cuda_bf16.h>
#include <cstdint>

#define N_B 32
#define S_LEN 1024
#define HEADS 4
#define HD 32
#define EMB 128
#define LOG2E 1.4426950408889634f
#define SCALE 0.08838834764831845f      // 1/sqrt(128)
#define QSCALE (SCALE * LOG2E)

// ---------------- device scratch ----------------
__device__ __nv_bfloat16 g_qhi[N_B*HEADS*S_LEN*HD];
__device__ __nv_bfloat16 g_khi[N_B*HEADS*S_LEN*HD];
__device__ __nv_bfloat16 g_vhi[N_B*HEADS*S_LEN*HD];
__device__ __nv_bfloat16 g_vlo[N_B*HEADS*S_LEN*HD];
__device__ uint32_t g_mbits[(size_t)N_B*S_LEN*(S_LEN/32)];
__device__ uint32_t g_cxhi[(size_t)N_B*S_LEN*64];    // ctx bf16x2 (even,odd cols)
__device__ uint32_t g_cxlo[(size_t)N_B*S_LEN*64];
__device__ __nv_bfloat16 g_wohi[EMB*EMB];
__device__ __nv_bfloat16 g_wolo[EMB*EMB];

// ---------------- helpers ----------------
__device__ __forceinline__ uint32_t smem_u32(const void* p){
    uint32_t a;
    asm("{ .reg .u64 t; cvta.to.shared.u64 t, %1; cvt.u32.u64 %0, t; }" : "=r"(a) : "l"(p));
    return a;
}
__device__ __forceinline__ float ex2f(float x){
    float y; asm("ex2.approx.f32 %0, %1;" : "=f"(y) : "f"(x)); return y;
}
__device__ __forceinline__ uint32_t packbf(float lo, float hi){
    uint32_t d; asm("cvt.rn.bf16x2.f32 %0, %1, %2;" : "=r"(d) : "f"(hi), "f"(lo)); return d;
}
__device__ __forceinline__ void ldsm_x4(uint32_t* r, uint32_t addr){
    asm volatile("ldmatrix.sync.aligned.m8n8.x4.shared.b16 {%0,%1,%2,%3}, [%4];"
        : "=r"(r[0]), "=r"(r[1]), "=r"(r[2]), "=r"(r[3]) : "r"(addr));
}
__device__ __forceinline__ void ldsm_x4t(uint32_t* r, uint32_t addr){
    asm volatile("ldmatrix.sync.aligned.m8n8.x4.trans.shared.b16 {%0,%1,%2,%3}, [%4];"
        : "=r"(r[0]), "=r"(r[1]), "=r"(r[2]), "=r"(r[3]) : "r"(addr));
}
__device__ __forceinline__ void mma16816(float* c, const uint32_t* a, const uint32_t* b){
    asm volatile("mma.sync.aligned.m16n8k16.row.col.f32.bf16.bf16.f32 "
        "{%0,%1,%2,%3}, {%4,%5,%6,%7}, {%8,%9}, {%0,%1,%2,%3};"
        : "+f"(c[0]), "+f"(c[1]), "+f"(c[2]), "+f"(c[3])
        : "r"(a[0]), "r"(a[1]), "r"(a[2]), "r"(a[3]), "r"(b[0]), "r"(b[1]));
}
__device__ __forceinline__ void cp_async16(uint32_t dst, const void* src){
    asm volatile("cp.async.cg.shared.global [%0], [%1], 16;" :: "r"(dst), "l"(src));
}
#define CP_COMMIT() asm volatile("cp.async.commit_group;" ::: "memory")

// ---------------- attn smem layout (byte offsets; row stride 80B) ----------------
#define RS 80
#define BUF 10240
#define SM_K0  0
#define SM_VH0 20480
#define SM_VL0 40960
#define SM_Q   61440
#define SM_MB0 71680
#define SM_TOTAL 76800

// ============================================================
// Kernel 0a: bit-pack the mask
// ============================================================
__global__ __launch_bounds__(256) void maskbits_kernel(const int* __restrict__ mask)
{
    size_t w = (size_t)blockIdx.x * 256 + threadIdx.x;
    const int4* p = (const int4*)(mask + w * 32);
    uint32_t b = 0;
    #pragma unroll
    for (int i = 0; i < 8; i++){
        int4 v = __ldg(p + i);
        b |= (v.x != 0 ? 1u : 0u) << (i*4 + 0);
        b |= (v.y != 0 ? 1u : 0u) << (i*4 + 1);
        b |= (v.z != 0 ? 1u : 0u) << (i*4 + 2);
        b |= (v.w != 0 ? 1u : 0u) << (i*4 + 3);
    }
    g_mbits[w] = b;
}

// ============================================================
// Kernel 0b: split Wo into bf16 hi/lo
// ============================================================
__global__ __launch_bounds__(256) void woprep_kernel(const float* __restrict__ Wo)
{
    int i = blockIdx.x * 256 + threadIdx.x;      // 16384
    float w = __ldg(Wo + i);
    __nv_bfloat16 hi = __float2bfloat16(w);
    g_wohi[i] = hi;
    g_wolo[i] = __float2bfloat16(w - __bfloat162float(hi));
}

// ============================================================
// Kernel 1: projections -> bf16 (Q pre-scaled by log2e/sqrt(128)); V hi/lo
// ============================================================
__global__ __launch_bounds__(128) void proj_kernel(
    const float* __restrict__ vin, const float* __restrict__ kin,
    const float* __restrict__ qin,
    const float* __restrict__ Wv, const float* __restrict__ Wk,
    const float* __restrict__ Wq)
{
    __shared__ float sW[3][32*33];
    __shared__ float srow[3][16*128];
    int t = threadIdx.x;
    for (int i = t; i < 1024; i += 128){
        int d = i >> 5, e = i & 31;
        sW[0][d*33+e] = __ldg(Wv + i);
        sW[1][d*33+e] = __ldg(Wk + i);
        sW[2][d*33+e] = __ldg(Wq + i);
    }
    int row0 = blockIdx.x * 16;
    const float4* s0 = (const float4*)(vin + (size_t)row0*128);
    const float4* s1 = (const float4*)(kin + (size_t)row0*128);
    const float4* s2 = (const float4*)(qin + (size_t)row0*128);
    #pragma unroll
    for (int i = 0; i < 4; i++){
        int idx = t + i*128;
        ((float4*)srow[0])[idx] = __ldg(s0 + idx);
        ((float4*)srow[1])[idx] = __ldg(s1 + idx);
        ((float4*)srow[2])[idx] = __ldg(s2 + idx);
    }
    __syncthreads();
    int h = t >> 5, d = t & 31;
    int n = row0 >> 10;
    int sbase = row0 & 1023;
    for (int i = 0; i < 16; i++){
        float av = 0.f, ak = 0.f, aq = 0.f;
        const float* rv = &srow[0][i*128 + h*32];
        const float* rk = &srow[1][i*128 + h*32];
        const float* rq = &srow[2][i*128 + h*32];
        #pragma unroll
        for (int e = 0; e < 32; e++){
            av = fmaf(sW[0][d*33+e], rv[e], av);
            ak = fmaf(sW[1][d*33+e], rk[e], ak);
            aq = fmaf(sW[2][d*33+e], rq[e], aq);
        }
        __nv_bfloat16 vh = __float2bfloat16(av);
        size_t o = ((size_t)(n*HEADS + h)*S_LEN + sbase + i)*HD + d;
        g_qhi[o] = __float2bfloat16(aq * QSCALE);
        g_khi[o] = __float2bfloat16(ak);
        g_vhi[o] = vh;
        g_vlo[o] = __float2bfloat16(av - __bfloat162float(vh));
    }
}

// ============================================================
// Kernel 2: fused HMMA attention, cp.async double-buffered.
// CTA = (n,h,128 q-rows), 256 thr, 8 warps x m16.
// ============================================================
__global__ __launch_bounds__(256, 1) void attn_kernel(float* __restrict__ attw)
{
    extern __shared__ char sm[];
    uint32_t smb = smem_u32(sm);
    int t = threadIdx.x;
    int l = t & 31, w = t >> 5;
    int bid = blockIdx.x;
    int qt = bid & 7, h = (bid >> 3) & 3, n = bid >> 5;   // qt fastest: K/V L2 reuse
    int nh = n*HEADS + h;
    size_t hoff = (size_t)nh * S_LEN * HD;
    int qrow0 = qt * 128;
    int wm0 = w * 16;
    int g = l >> 2, u = l & 3;

    // ---- stage Q tile into smem (plain stores), load persistent A-frags
    #pragma unroll
    for (int i = 0; i < 2; i++){
        int idx = t + i*256;
        int row = idx >> 2, part = idx & 3;
        const char* qsrc = (const char*)(g_qhi + hoff + (size_t)(qrow0+row)*HD) + part*16;
        *(uint4*)(sm + SM_Q + row*RS + part*16) = *(const uint4*)qsrc;
    }

    // ---- prefetch tile 0
    {
        const char* ksrc = (const char*)(g_khi + hoff);
        const char* vhsrc = (const char*)(g_vhi + hoff);
        const char* vlsrc = (const char*)(g_vlo + hoff);
        #pragma unroll
        for (int i = 0; i < 2; i++){
            int idx = t + i*256;
            int row = idx >> 2, part = idx & 3;
            int go = row*64 + part*16, so = row*RS + part*16;
            cp_async16(smb + SM_K0  + so, ksrc + go);
            cp_async16(smb + SM_VH0 + so, vhsrc + go);
            cp_async16(smb + SM_VL0 + so, vlsrc + go);
        }
        if (t < 128)
            cp_async16(smb + SM_MB0 + t*16,
                       g_mbits + ((size_t)n*S_LEN + qrow0 + t)*32);
        CP_COMMIT();
    }
    __syncthreads();

    uint32_t qh0[4], qh1[4];
    {
        uint32_t rowb = (uint32_t)((wm0 + ((l & 8) ? 8 : 0) + (l & 7))*RS + ((l & 16) ? 16 : 0));
        ldsm_x4(qh0, smb + SM_Q + rowb);        // k 0-15
        ldsm_x4(qh1, smb + SM_Q + rowb + 32);   // k 16-31
    }

    float pv[4][4];
    #pragma unroll
    for (int i = 0; i < 4; i++){ pv[i][0]=0.f; pv[i][1]=0.f; pv[i][2]=0.f; pv[i][3]=0.f; }
    float l_r = 0.f, l_r8 = 0.f, inv_r = 0.f, inv_r8 = 0.f;

    float* wbase = attw + ((size_t)nh * S_LEN + qrow0) * S_LEN;

    for (int it = 0; it < 16; it++){
        int sweep = it >> 3, kt = it & 7, buf = it & 1;

        // ---- prefetch next tile into buf^1
        if (it < 15){
            int it2 = it + 1;
            int sw2 = it2 >> 3, kt2 = it2 & 7, b2 = it2 & 1;
            const char* ksrc = (const char*)(g_khi + hoff + (size_t)kt2*128*HD);
            const char* vhsrc = (const char*)(g_vhi + hoff + (size_t)kt2*128*HD);
            const char* vlsrc = (const char*)(g_vlo + hoff + (size_t)kt2*128*HD);
            #pragma unroll
            for (int i = 0; i < 2; i++){
                int idx = t + i*256;
                int row = idx >> 2, part = idx & 3;
                int go = row*64 + part*16, so = row*RS + part*16;
                cp_async16(smb + SM_K0 + b2*BUF + so, ksrc + go);
                if (sw2 == 0){
                    cp_async16(smb + SM_VH0 + b2*BUF + so, vhsrc + go);
                    cp_async16(smb + SM_VL0 + b2*BUF + so, vlsrc + go);
                }
            }
            if (t < 128)
                cp_async16(smb + SM_MB0 + b2*2048 + t*16,
                           g_mbits + ((size_t)n*S_LEN + qrow0 + t)*32 + kt2*4);
            CP_COMMIT();
            asm volatile("cp.async.wait_group 1;" ::: "memory");
        } else {
            asm volatile("cp.async.wait_group 0;" ::: "memory");
        }
        __syncthreads();

        uint32_t kbase  = smb + SM_K0  + buf*BUF;
        uint32_t vhbase = smb + SM_VH0 + buf*BUF;
        uint32_t vlbase = smb + SM_VL0 + buf*BUF;
        const uint32_t* mb = (const uint32_t*)(sm + SM_MB0 + buf*2048);

        // ---- QK^T hi-only: 16 n-tiles
        float qk[16][4];
        #pragma unroll
        for (int i = 0; i < 16; i++){ qk[i][0]=0.f; qk[i][1]=0.f; qk[i][2]=0.f; qk[i][3]=0.f; }
        #pragma unroll
        for (int np = 0; np < 8; np++){
            uint32_t bh0[4], bh1[4];
            uint32_t rb = (uint32_t)((np*16 + ((l & 16) ? 8 : 0) + (l & 7))*RS + ((l & 8) ? 16 : 0));
            ldsm_x4(bh0, kbase + rb);
            ldsm_x4(bh1, kbase + rb + 32);
            mma16816(qk[2*np],   qh0, bh0);     mma16816(qk[2*np+1], qh0, bh0+2);
            mma16816(qk[2*np],   qh1, bh1);     mma16816(qk[2*np+1], qh1, bh1+2);
        }

        uint32_t wr[4], wr8[4];
        #pragma unroll
        for (int j = 0; j < 4; j++){
            wr[j]  = mb[g*4 + j];
            wr8[j] = mb[(g+8)*4 + j];
        }

        if (sweep == 0){
            uint32_t ehi[32], elo[32];
            #pragma unroll
            for (int nt = 0; nt < 16; nt++){
                int wj = nt >> 2;
                int sh = (nt & 3)*8 + u*2;
                float e0 = ((wr[wj]  >> sh)     & 1) ? ex2f(qk[nt][0]) : 0.f;
                float e1 = ((wr[wj]  >> (sh+1)) & 1) ? ex2f(qk[nt][1]) : 0.f;
                float e2 = ((wr8[wj] >> sh)     & 1) ? ex2f(qk[nt][2]) : 0.f;
                float e3 = ((wr8[wj] >> (sh+1)) & 1) ? ex2f(qk[nt][3]) : 0.f;
                l_r  += e0 + e1;
                l_r8 += e2 + e3;
                uint32_t p0 = packbf(e0, e1);
                uint32_t p1 = packbf(e2, e3);
                ehi[2*nt]   = p0;
                ehi[2*nt+1] = p1;
                float r0 = e0 - __uint_as_float(p0 << 16);
                float r1 = e1 - __uint_as_float(p0 & 0xffff0000u);
                float r2 = e2 - __uint_as_float(p1 << 16);
                float r3 = e3 - __uint_as_float(p1 & 0xffff0000u);
                elo[2*nt]   = packbf(r0, r1);
                elo[2*nt+1] = packbf(r2, r3);
            }
            // ---- PV 3-term: ah*vh + al*vh + ah*vl
            #pragma unroll
            for (int kc = 0; kc < 8; kc++){
                uint32_t vh0[4], vh1[4], vl0[4], vl1[4];
                uint32_t rb = (uint32_t)((kc*16 + ((l & 8) ? 8 : 0) + (l & 7))*RS + ((l & 16) ? 16 : 0));
                ldsm_x4t(vh0, vhbase + rb);
                ldsm_x4t(vh1, vhbase + rb + 32);
                ldsm_x4t(vl0, vlbase + rb);
                ldsm_x4t(vl1, vlbase + rb + 32);
                const uint32_t* ah = &ehi[4*kc];
                const uint32_t* al = &elo[4*kc];
                mma16816(pv[0], ah, vh0);   mma16816(pv[1], ah, vh0+2);
                mma16816(pv[2], ah, vh1);   mma16816(pv[3], ah, vh1+2);
                mma16816(pv[0], al, vh0);   mma16816(pv[1], al, vh0+2);
                mma16816(pv[2], al, vh1);   mma16816(pv[3], al, vh1+2);
                mma16816(pv[0], ah, vl0);   mma16816(pv[1], ah, vl0+2);
                mma16816(pv[2], ah, vl1);   mma16816(pv[3], ah, vl1+2);
            }
        } else {
            float* wr0p = wbase + (size_t)(wm0 + g)*S_LEN     + kt*128 + u*2;
            float* wr8p = wbase + (size_t)(wm0 + g + 8)*S_LEN + kt*128 + u*2;
            #pragma unroll
            for (int nt = 0; nt < 16; nt++){
                int wj = nt >> 2;
                int sh = (nt & 3)*8 + u*2;
                float e0 = ((wr[wj]  >> sh)     & 1) ? ex2f(qk[nt][0]) : 0.f;
                float e1 = ((wr[wj]  >> (sh+1)) & 1) ? ex2f(qk[nt][1]) : 0.f;
                float e2 = ((wr8[wj] >> sh)     & 1) ? ex2f(qk[nt][2]) : 0.f;
                float e3 = ((wr8[wj] >> (sh+1)) & 1) ? ex2f(qk[nt][3]) : 0.f;
                float2 o0; o0.x = e0*inv_r;  o0.y = e1*inv_r;
                float2 o1; o1.x = e2*inv_r8; o1.y = e3*inv_r8;
                *(float2*)(wr0p + nt*8) = o0;
                *(float2*)(wr8p + nt*8) = o1;
            }
        }

        if (it == 7){
            // row-sum reduction + normalized ctx write (bf16 hi/lo packed)
            l_r  += __shfl_xor_sync(0xffffffffu, l_r, 1);
            l_r  += __shfl_xor_sync(0xffffffffu, l_r, 2);
            l_r8 += __shfl_xor_sync(0xffffffffu, l_r8, 1);
            l_r8 += __shfl_xor_sync(0xffffffffu, l_r8, 2);
            inv_r  = 1.0f / l_r;
            inv_r8 = 1.0f / l_r8;
            size_t r0 = (size_t)(n*S_LEN + qrow0 + wm0 + g);
            size_t r8 = r0 + 8;
            #pragma unroll
            for (int nt = 0; nt < 4; nt++){
                float x0 = pv[nt][0]*inv_r,  x1 = pv[nt][1]*inv_r;
                float x2 = pv[nt][2]*inv_r8, x3 = pv[nt][3]*inv_r8;
                uint32_t h0 = packbf(x0, x1);
                uint32_t h1 = packbf(x2, x3);
                uint32_t l0 = packbf(x0 - __uint_as_float(h0 << 16),
                                     x1 - __uint_as_float(h0 & 0xffff0000u));
                uint32_t l1 = packbf(x2 - __uint_as_float(h1 << 16),
                                     x3 - __uint_as_float(h1 & 0xffff0000u));
                int ci = h*16 + nt*4 + u;
                g_cxhi[r0*64 + ci] = h0;
                g_cxlo[r0*64 + ci] = l0;
                g_cxhi[r8*64 + ci] = h1;
                g_cxlo[r8*64 + ci] = l1;
            }
        }
        __syncthreads();
    }
}

// ============================================================
// Kernel 3: out = ctx @ Wo.T + bo via HMMA (ctx bf16 hi/lo, Wo hi/lo)
// CTA = 128 rows, 256 thr / 8 warps x m16; n = 128 cols = 16 n-tiles.
// Wo smem rows are 256B of data; stride ORS=272 (R8 bug was ORS=144).
// ============================================================
#define ORS 272
__global__ __launch_bounds__(256) void out_kernel(
    const float* __restrict__ bo, float* __restrict__ out)
{
    extern __shared__ char sm[];
    uint32_t smb = smem_u32(sm);
    char* swhi = sm;                   // 128 rows x 272B stride (256B data)
    char* swlo = sm + 128*ORS;
    float* sbo = (float*)(sm + 2*128*ORS);
    int t = threadIdx.x;
    int l = t & 31, w = t >> 5;
    int g = l >> 2, u = l & 3;

    #pragma unroll
    for (int i = 0; i < 8; i++){
        int idx = t + i*256;               // 2048 uint4 chunks
        int row = idx >> 4, part = idx & 15;
        *(uint4*)(swhi + row*ORS + part*16) = ((const uint4*)g_wohi)[idx];
        *(uint4*)(swlo + row*ORS + part*16) = ((const uint4*)g_wolo)[idx];
    }
    if (t < 128) sbo[t] = __ldg(bo + t);
    __syncthreads();

    int R0 = blockIdx.x*128 + w*16;
    float c[16][4];
    #pragma unroll
    for (int i = 0; i < 16; i++){ c[i][0]=0.f; c[i][1]=0.f; c[i][2]=0.f; c[i][3]=0.f; }

    #pragma unroll
    for (int c8 = 0; c8 < 8; c8++){        // k chunks of 16
        uint32_t ah[4], al[4];
        size_t rA = (size_t)(R0 + g)*64 + c8*8 + u;
        size_t rB = (size_t)(R0 + g + 8)*64 + c8*8 + u;
        ah[0] = __ldg(g_cxhi + rA);     ah[1] = __ldg(g_cxhi + rB);
        ah[2] = __ldg(g_cxhi + rA + 4); ah[3] = __ldg(g_cxhi + rB + 4);
        al[0] = __ldg(g_cxlo + rA);     al[1] = __ldg(g_cxlo + rB);
        al[2] = __ldg(g_cxlo + rA + 4); al[3] = __ldg(g_cxlo + rB + 4);
        #pragma unroll
        for (int np = 0; np < 8; np++){    // 8 ldsm x4 -> 16 n-tiles
            uint32_t bh[4], bl[4];
            uint32_t rb = (uint32_t)((np*16 + ((l & 16) ? 8 : 0) + (l & 7))*ORS + ((l & 8) ? 16 : 0) + c8*32);
            ldsm_x4(bh, smb + rb);
            ldsm_x4(bl, smb + 128*ORS + rb);
            mma16816(c[2*np],   ah, bh);     mma16816(c[2*np+1], ah, bh+2);
            mma16816(c[2*np],   al, bh);     mma16816(c[2*np+1], al, bh+2);
            mma16816(c[2*np],   ah, bl);     mma16816(c[2*np+1], ah, bl+2);
        }
    }

    float* o0 = out + (size_t)(R0 + g)*EMB + u*2;
    float* o8 = out + (size_t)(R0 + g + 8)*EMB + u*2;
    #pragma unroll
    for (int nt = 0; nt < 16; nt++){
        int col = nt*8 + u*2;
        float2 a; a.x = c[nt][0] + sbo[col]; a.y = c[nt][1] + sbo[col+1];
        float2 b; b.x = c[nt][2] + sbo[col]; b.y = c[nt][3] + sbo[col+1];
        *(float2*)(o0 + nt*8) = a;
        *(float2*)(o8 + nt*8) = b;
    }
}

// ============================================================
extern "C" void kernel_launch(void* const* d_in, const int* in_sizes, int n_in,
                              void* d_out, int out_size)
{
    const float* values = (const float*)d_in[0];
    const float* keys   = (const float*)d_in[1];
    const float* query  = (const float*)d_in[2];
    const int*   mask   = (const int*)d_in[3];
    const float* Wv     = (const float*)d_in[4];
    const float* Wk     = (const float*)d_in[5];
    const float* Wq     = (const float*)d_in[6];
    const float* Wo     = (const float*)d_in[7];
    const float* bo     = (const float*)d_in[8];

    float* out  = (float*)d_out;
    float* attw = out + (size_t)N_B*S_LEN*EMB;   // tuple order: (out, attention_weights)

    cudaFuncSetAttribute(attn_kernel, cudaFuncAttributeMaxDynamicSharedMemorySize, SM_TOTAL);
    cudaFuncSetAttribute(out_kernel,  cudaFuncAttributeMaxDynamicSharedMemorySize, 2*128*ORS + 512);

    maskbits_kernel<<<(N_B*S_LEN*(S_LEN/32))/256, 256>>>(mask);
    woprep_kernel<<<EMB*EMB/256, 256>>>(Wo);
    proj_kernel<<<(N_B*S_LEN)/16, 128>>>(values, keys, query, Wv, Wk, Wq);
    attn_kernel<<<N_B*HEADS*(S_LEN/128), 256, SM_TOTAL>>>(attw);
    out_kernel<<<(N_B*S_LEN)/128, 256, 2*128*ORS + 512>>>(bo, out);
}

// round 13
// speedup vs baseline: 5.5700x; 1.1747x over previous
#include <cuda_runtime.h>
#include <cuda_bf16.h>
#include <cstdint>

#define N_B 32
#define S_LEN 1024
#define HEADS 4
#define HD 32
#define EMB 128
#define LOG2E 1.4426950408889634f
#define SCALE 0.08838834764831845f      // 1/sqrt(128)
#define QSCALE (SCALE * LOG2E)

// ---------------- device scratch ----------------
__device__ __nv_bfloat16 g_qhi[N_B*HEADS*S_LEN*HD];
__device__ __nv_bfloat16 g_khi[N_B*HEADS*S_LEN*HD];
__device__ __nv_bfloat16 g_vhi[N_B*HEADS*S_LEN*HD];
__device__ __nv_bfloat16 g_vlo[N_B*HEADS*S_LEN*HD];
__device__ uint32_t g_mbits[(size_t)N_B*S_LEN*(S_LEN/32)];
__device__ uint32_t g_cxhi[(size_t)N_B*S_LEN*64];    // ctx bf16x2 (even,odd cols)
__device__ uint32_t g_cxlo[(size_t)N_B*S_LEN*64];
__device__ __nv_bfloat16 g_wohi[EMB*EMB];
__device__ __nv_bfloat16 g_wolo[EMB*EMB];

// ---------------- helpers ----------------
__device__ __forceinline__ uint32_t smem_u32(const void* p){
    uint32_t a;
    asm("{ .reg .u64 t; cvta.to.shared.u64 t, %1; cvt.u32.u64 %0, t; }" : "=r"(a) : "l"(p));
    return a;
}
__device__ __forceinline__ float ex2f(float x){
    float y; asm("ex2.approx.f32 %0, %1;" : "=f"(y) : "f"(x)); return y;
}
__device__ __forceinline__ uint32_t packbf(float lo, float hi){
    uint32_t d; asm("cvt.rn.bf16x2.f32 %0, %1, %2;" : "=r"(d) : "f"(hi), "f"(lo)); return d;
}
__device__ __forceinline__ void ldsm_x4(uint32_t* r, uint32_t addr){
    asm volatile("ldmatrix.sync.aligned.m8n8.x4.shared.b16 {%0,%1,%2,%3}, [%4];"
        : "=r"(r[0]), "=r"(r[1]), "=r"(r[2]), "=r"(r[3]) : "r"(addr));
}
__device__ __forceinline__ void ldsm_x4t(uint32_t* r, uint32_t addr){
    asm volatile("ldmatrix.sync.aligned.m8n8.x4.trans.shared.b16 {%0,%1,%2,%3}, [%4];"
        : "=r"(r[0]), "=r"(r[1]), "=r"(r[2]), "=r"(r[3]) : "r"(addr));
}
__device__ __forceinline__ void mma16816(float* c, const uint32_t* a, const uint32_t* b){
    asm volatile("mma.sync.aligned.m16n8k16.row.col.f32.bf16.bf16.f32 "
        "{%0,%1,%2,%3}, {%4,%5,%6,%7}, {%8,%9}, {%0,%1,%2,%3};"
        : "+f"(c[0]), "+f"(c[1]), "+f"(c[2]), "+f"(c[3])
        : "r"(a[0]), "r"(a[1]), "r"(a[2]), "r"(a[3]), "r"(b[0]), "r"(b[1]));
}
__device__ __forceinline__ void cp_async16(uint32_t dst, const void* src){
    asm volatile("cp.async.cg.shared.global [%0], [%1], 16;" :: "r"(dst), "l"(src));
}
#define CP_COMMIT() asm volatile("cp.async.commit_group;" ::: "memory")

// ---------------- attn smem layout (byte offsets; row stride 80B) ----------------
#define RS 80
#define BUF 10240
#define SM_K0  0
#define SM_VH0 20480
#define SM_VL0 40960
#define SM_Q   61440
#define SM_MB0 71680
#define SM_TOTAL 76800

// ============================================================
// Kernel 0a: bit-pack the mask
// ============================================================
__global__ __launch_bounds__(256) void maskbits_kernel(const int* __restrict__ mask)
{
    size_t w = (size_t)blockIdx.x * 256 + threadIdx.x;
    const int4* p = (const int4*)(mask + w * 32);
    uint32_t b = 0;
    #pragma unroll
    for (int i = 0; i < 8; i++){
        int4 v = __ldg(p + i);
        b |= (v.x != 0 ? 1u : 0u) << (i*4 + 0);
        b |= (v.y != 0 ? 1u : 0u) << (i*4 + 1);
        b |= (v.z != 0 ? 1u : 0u) << (i*4 + 2);
        b |= (v.w != 0 ? 1u : 0u) << (i*4 + 3);
    }
    g_mbits[w] = b;
}

// ============================================================
// Kernel 0b: split Wo into bf16 hi/lo
// ============================================================
__global__ __launch_bounds__(256) void woprep_kernel(const float* __restrict__ Wo)
{
    int i = blockIdx.x * 256 + threadIdx.x;      // 16384
    float w = __ldg(Wo + i);
    __nv_bfloat16 hi = __float2bfloat16(w);
    g_wohi[i] = hi;
    g_wolo[i] = __float2bfloat16(w - __bfloat162float(hi));
}

// ============================================================
// Kernel 1: projections -> bf16 (Q pre-scaled); 256 thr, 2 half-blocks x 8 rows
// ============================================================
__global__ __launch_bounds__(256) void proj_kernel(
    const float* __restrict__ vin, const float* __restrict__ kin,
    const float* __restrict__ qin,
    const float* __restrict__ Wv, const float* __restrict__ Wk,
    const float* __restrict__ Wq)
{
    __shared__ float sW[3][32*33];
    __shared__ float srow[3][16*128];
    int t = threadIdx.x;
    for (int i = t; i < 1024; i += 256){
        int d = i >> 5, e = i & 31;
        sW[0][d*33+e] = __ldg(Wv + i);
        sW[1][d*33+e] = __ldg(Wk + i);
        sW[2][d*33+e] = __ldg(Wq + i);
    }
    int row0 = blockIdx.x * 16;
    const float4* s0 = (const float4*)(vin + (size_t)row0*128);
    const float4* s1 = (const float4*)(kin + (size_t)row0*128);
    const float4* s2 = (const float4*)(qin + (size_t)row0*128);
    #pragma unroll
    for (int i = 0; i < 2; i++){
        int idx = t + i*256;
        ((float4*)srow[0])[idx] = __ldg(s0 + idx);
        ((float4*)srow[1])[idx] = __ldg(s1 + idx);
        ((float4*)srow[2])[idx] = __ldg(s2 + idx);
    }
    __syncthreads();
    int half = t >> 7;                  // 0: rows 0-7, 1: rows 8-15
    int tt = t & 127;
    int h = tt >> 5, d = tt & 31;
    int n = row0 >> 10;
    int sbase = (row0 & 1023) + half*8;
    for (int i = 0; i < 8; i++){
        int ri = half*8 + i;
        float av = 0.f, ak = 0.f, aq = 0.f;
        const float* rv = &srow[0][ri*128 + h*32];
        const float* rk = &srow[1][ri*128 + h*32];
        const float* rq = &srow[2][ri*128 + h*32];
        #pragma unroll
        for (int e = 0; e < 32; e++){
            av = fmaf(sW[0][d*33+e], rv[e], av);
            ak = fmaf(sW[1][d*33+e], rk[e], ak);
            aq = fmaf(sW[2][d*33+e], rq[e], aq);
        }
        __nv_bfloat16 vh = __float2bfloat16(av);
        size_t o = ((size_t)(n*HEADS + h)*S_LEN + sbase + i)*HD + d;
        g_qhi[o] = __float2bfloat16(aq * QSCALE);
        g_khi[o] = __float2bfloat16(ak);
        g_vhi[o] = vh;
        g_vlo[o] = __float2bfloat16(av - __bfloat162float(vh));
    }
}

// ============================================================
// Kernel 2: fused HMMA attention, cp.async double-buffered,
// per-chunk QK->exp->PV fusion (low register pressure).
// NOTE: no minBlocksPerMultiprocessor bound — R11/R12's (256,2)
// forced ≤128 regs and is the suspected ptxas-timeout trigger.
// ============================================================
__global__ __launch_bounds__(256) void attn_kernel(float* __restrict__ attw)
{
    extern __shared__ char sm[];
    uint32_t smb = smem_u32(sm);
    int t = threadIdx.x;
    int l = t & 31, w = t >> 5;
    int bid = blockIdx.x;
    int qt = bid & 7, h = (bid >> 3) & 3, n = bid >> 5;   // qt fastest: K/V L2 reuse
    int nh = n*HEADS + h;
    size_t hoff = (size_t)nh * S_LEN * HD;
    int qrow0 = qt * 128;
    int wm0 = w * 16;
    int g = l >> 2, u = l & 3;

    // ---- stage Q tile into smem, load persistent A-frags
    #pragma unroll
    for (int i = 0; i < 2; i++){
        int idx = t + i*256;
        int row = idx >> 2, part = idx & 3;
        const char* qsrc = (const char*)(g_qhi + hoff + (size_t)(qrow0+row)*HD) + part*16;
        *(uint4*)(sm + SM_Q + row*RS + part*16) = *(const uint4*)qsrc;
    }

    // ---- prefetch tile 0
    {
        const char* ksrc = (const char*)(g_khi + hoff);
        const char* vhsrc = (const char*)(g_vhi + hoff);
        const char* vlsrc = (const char*)(g_vlo + hoff);
        #pragma unroll
        for (int i = 0; i < 2; i++){
            int idx = t + i*256;
            int row = idx >> 2, part = idx & 3;
            int go = row*64 + part*16, so = row*RS + part*16;
            cp_async16(smb + SM_K0  + so, ksrc + go);
            cp_async16(smb + SM_VH0 + so, vhsrc + go);
            cp_async16(smb + SM_VL0 + so, vlsrc + go);
        }
        if (t < 128)
            cp_async16(smb + SM_MB0 + t*16,
                       g_mbits + ((size_t)n*S_LEN + qrow0 + t)*32);
        CP_COMMIT();
    }
    __syncthreads();

    uint32_t qh0[4], qh1[4];
    {
        uint32_t rowb = (uint32_t)((wm0 + ((l & 8) ? 8 : 0) + (l & 7))*RS + ((l & 16) ? 16 : 0));
        ldsm_x4(qh0, smb + SM_Q + rowb);        // k 0-15
        ldsm_x4(qh1, smb + SM_Q + rowb + 32);   // k 16-31
    }

    float pv[4][4];
    #pragma unroll
    for (int i = 0; i < 4; i++){ pv[i][0]=0.f; pv[i][1]=0.f; pv[i][2]=0.f; pv[i][3]=0.f; }
    float l_r = 0.f, l_r8 = 0.f, inv_r = 0.f, inv_r8 = 0.f;

    float* wbase = attw + ((size_t)nh * S_LEN + qrow0) * S_LEN;

    for (int it = 0; it < 16; it++){
        int sweep = it >> 3, kt = it & 7, buf = it & 1;

        // ---- prefetch next tile into buf^1
        if (it < 15){
            int it2 = it + 1;
            int sw2 = it2 >> 3, kt2 = it2 & 7, b2 = it2 & 1;
            const char* ksrc = (const char*)(g_khi + hoff + (size_t)kt2*128*HD);
            const char* vhsrc = (const char*)(g_vhi + hoff + (size_t)kt2*128*HD);
            const char* vlsrc = (const char*)(g_vlo + hoff + (size_t)kt2*128*HD);
            #pragma unroll
            for (int i = 0; i < 2; i++){
                int idx = t + i*256;
                int row = idx >> 2, part = idx & 3;
                int go = row*64 + part*16, so = row*RS + part*16;
                cp_async16(smb + SM_K0 + b2*BUF + so, ksrc + go);
                if (sw2 == 0){
                    cp_async16(smb + SM_VH0 + b2*BUF + so, vhsrc + go);
                    cp_async16(smb + SM_VL0 + b2*BUF + so, vlsrc + go);
                }
            }
            if (t < 128)
                cp_async16(smb + SM_MB0 + b2*2048 + t*16,
                           g_mbits + ((size_t)n*S_LEN + qrow0 + t)*32 + kt2*4);
            CP_COMMIT();
            asm volatile("cp.async.wait_group 1;" ::: "memory");
        } else {
            asm volatile("cp.async.wait_group 0;" ::: "memory");
        }
        __syncthreads();

        uint32_t kbase  = smb + SM_K0  + buf*BUF;
        uint32_t vhbase = smb + SM_VH0 + buf*BUF;
        uint32_t vlbase = smb + SM_VL0 + buf*BUF;
        const uint32_t* mb = (const uint32_t*)(sm + SM_MB0 + buf*2048);

        if (sweep == 0){
            // ---- fused per-16-key chunk: QK -> mask/exp -> pack -> PV
            #pragma unroll
            for (int kc = 0; kc < 8; kc++){
                uint32_t bh0[4], bh1[4];
                uint32_t rbk = (uint32_t)((kc*16 + ((l & 16) ? 8 : 0) + (l & 7))*RS + ((l & 8) ? 16 : 0));
                ldsm_x4(bh0, kbase + rbk);
                ldsm_x4(bh1, kbase + rbk + 32);
                float qk0[4] = {0.f,0.f,0.f,0.f};
                float qk1[4] = {0.f,0.f,0.f,0.f};
                mma16816(qk0, qh0, bh0);   mma16816(qk1, qh0, bh0+2);
                mma16816(qk0, qh1, bh1);   mma16816(qk1, qh1, bh1+2);

                uint32_t w0 = mb[g*4 + (kc >> 1)];
                uint32_t w8 = mb[(g+8)*4 + (kc >> 1)];
                int sh0 = ((2*kc) & 3)*8 + u*2;
                int sh1 = ((2*kc+1) & 3)*8 + u*2;
                float e0 = ((w0 >> sh0)     & 1) ? ex2f(qk0[0]) : 0.f;
                float e1 = ((w0 >> (sh0+1)) & 1) ? ex2f(qk0[1]) : 0.f;
                float e2 = ((w8 >> sh0)     & 1) ? ex2f(qk0[2]) : 0.f;
                float e3 = ((w8 >> (sh0+1)) & 1) ? ex2f(qk0[3]) : 0.f;
                float e4 = ((w0 >> sh1)     & 1) ? ex2f(qk1[0]) : 0.f;
                float e5 = ((w0 >> (sh1+1)) & 1) ? ex2f(qk1[1]) : 0.f;
                float e6 = ((w8 >> sh1)     & 1) ? ex2f(qk1[2]) : 0.f;
                float e7 = ((w8 >> (sh1+1)) & 1) ? ex2f(qk1[3]) : 0.f;
                l_r  += e0 + e1 + e4 + e5;
                l_r8 += e2 + e3 + e6 + e7;

                uint32_t ah[4], al[4];
                ah[0] = packbf(e0, e1);
                ah[1] = packbf(e2, e3);
                ah[2] = packbf(e4, e5);
                ah[3] = packbf(e6, e7);
                al[0] = packbf(e0 - __uint_as_float(ah[0] << 16), e1 - __uint_as_float(ah[0] & 0xffff0000u));
                al[1] = packbf(e2 - __uint_as_float(ah[1] << 16), e3 - __uint_as_float(ah[1] & 0xffff0000u));
                al[2] = packbf(e4 - __uint_as_float(ah[2] << 16), e5 - __uint_as_float(ah[2] & 0xffff0000u));
                al[3] = packbf(e6 - __uint_as_float(ah[3] << 16), e7 - __uint_as_float(ah[3] & 0xffff0000u));

                uint32_t vh0[4], vh1[4], vl0[4], vl1[4];
                uint32_t rbv = (uint32_t)((kc*16 + ((l & 8) ? 8 : 0) + (l & 7))*RS + ((l & 16) ? 16 : 0));
                ldsm_x4t(vh0, vhbase + rbv);
                ldsm_x4t(vh1, vhbase + rbv + 32);
                ldsm_x4t(vl0, vlbase + rbv);
                ldsm_x4t(vl1, vlbase + rbv + 32);
                mma16816(pv[0], ah, vh0);   mma16816(pv[1], ah, vh0+2);
                mma16816(pv[2], ah, vh1);   mma16816(pv[3], ah, vh1+2);
                mma16816(pv[0], al, vh0);   mma16816(pv[1], al, vh0+2);
                mma16816(pv[2], al, vh1);   mma16816(pv[3], al, vh1+2);
                mma16816(pv[0], ah, vl0);   mma16816(pv[1], ah, vl0+2);
                mma16816(pv[2], ah, vl1);   mma16816(pv[3], ah, vl1+2);
            }
        } else {
            // ---- sweep 2: per-chunk QK -> exp -> normalized weights out
            #pragma unroll
            for (int np = 0; np < 8; np++){
                uint32_t bh0[4], bh1[4];
                uint32_t rbk = (uint32_t)((np*16 + ((l & 16) ? 8 : 0) + (l & 7))*RS + ((l & 8) ? 16 : 0));
                ldsm_x4(bh0, kbase + rbk);
                ldsm_x4(bh1, kbase + rbk + 32);
                float qk0[4] = {0.f,0.f,0.f,0.f};
                float qk1[4] = {0.f,0.f,0.f,0.f};
                mma16816(qk0, qh0, bh0);   mma16816(qk1, qh0, bh0+2);
                mma16816(qk0, qh1, bh1);   mma16816(qk1, qh1, bh1+2);

                uint32_t w0 = mb[g*4 + (np >> 1)];
                uint32_t w8 = mb[(g+8)*4 + (np >> 1)];
                int sh0 = ((2*np) & 3)*8 + u*2;
                int sh1 = ((2*np+1) & 3)*8 + u*2;
                float e0 = ((w0 >> sh0)     & 1) ? ex2f(qk0[0]) : 0.f;
                float e1 = ((w0 >> (sh0+1)) & 1) ? ex2f(qk0[1]) : 0.f;
                float e2 = ((w8 >> sh0)     & 1) ? ex2f(qk0[2]) : 0.f;
                float e3 = ((w8 >> (sh0+1)) & 1) ? ex2f(qk0[3]) : 0.f;
                float e4 = ((w0 >> sh1)     & 1) ? ex2f(qk1[0]) : 0.f;
                float e5 = ((w0 >> (sh1+1)) & 1) ? ex2f(qk1[1]) : 0.f;
                float e6 = ((w8 >> sh1)     & 1) ? ex2f(qk1[2]) : 0.f;
                float e7 = ((w8 >> (sh1+1)) & 1) ? ex2f(qk1[3]) : 0.f;

                float* wr0p = wbase + (size_t)(wm0 + g)*S_LEN     + kt*128 + np*16 + u*2;
                float* wr8p = wbase + (size_t)(wm0 + g + 8)*S_LEN + kt*128 + np*16 + u*2;
                float2 o;
                o.x = e0*inv_r;  o.y = e1*inv_r;  *(float2*)(wr0p) = o;
                o.x = e4*inv_r;  o.y = e5*inv_r;  *(float2*)(wr0p + 8) = o;
                o.x = e2*inv_r8; o.y = e3*inv_r8; *(float2*)(wr8p) = o;
                o.x = e6*inv_r8; o.y = e7*inv_r8; *(float2*)(wr8p + 8) = o;
            }
        }

        if (it == 7){
            // row-sum reduction + normalized ctx write (bf16 hi/lo packed)
            l_r  += __shfl_xor_sync(0xffffffffu, l_r, 1);
            l_r  += __shfl_xor_sync(0xffffffffu, l_r, 2);
            l_r8 += __shfl_xor_sync(0xffffffffu, l_r8, 1);
            l_r8 += __shfl_xor_sync(0xffffffffu, l_r8, 2);
            inv_r  = 1.0f / l_r;
            inv_r8 = 1.0f / l_r8;
            size_t r0 = (size_t)(n*S_LEN + qrow0 + wm0 + g);
            size_t r8 = r0 + 8;
            #pragma unroll
            for (int nt = 0; nt < 4; nt++){
                float x0 = pv[nt][0]*inv_r,  x1 = pv[nt][1]*inv_r;
                float x2 = pv[nt][2]*inv_r8, x3 = pv[nt][3]*inv_r8;
                uint32_t h0 = packbf(x0, x1);
                uint32_t h1 = packbf(x2, x3);
                uint32_t l0 = packbf(x0 - __uint_as_float(h0 << 16),
                                     x1 - __uint_as_float(h0 & 0xffff0000u));
                uint32_t l1 = packbf(x2 - __uint_as_float(h1 << 16),
                                     x3 - __uint_as_float(h1 & 0xffff0000u));
                int ci = h*16 + nt*4 + u;
                g_cxhi[r0*64 + ci] = h0;
                g_cxlo[r0*64 + ci] = l0;
                g_cxhi[r8*64 + ci] = h1;
                g_cxlo[r8*64 + ci] = l1;
            }
        }
        __syncthreads();
    }
}

// ============================================================
// Kernel 3: out = ctx @ Wo.T + bo via HMMA (ctx bf16 hi/lo, Wo hi/lo)
// ============================================================
#define ORS 272
__global__ __launch_bounds__(256) void out_kernel(
    const float* __restrict__ bo, float* __restrict__ out)
{
    extern __shared__ char sm[];
    uint32_t smb = smem_u32(sm);
    char* swhi = sm;                   // 128 rows x 272B stride (256B data)
    char* swlo = sm + 128*ORS;
    float* sbo = (float*)(sm + 2*128*ORS);
    int t = threadIdx.x;
    int l = t & 31, w = t >> 5;
    int g = l >> 2, u = l & 3;

    #pragma unroll
    for (int i = 0; i < 8; i++){
        int idx = t + i*256;               // 2048 uint4 chunks
        int row = idx >> 4, part = idx & 15;
        *(uint4*)(swhi + row*ORS + part*16) = ((const uint4*)g_wohi)[idx];
        *(uint4*)(swlo + row*ORS + part*16) = ((const uint4*)g_wolo)[idx];
    }
    if (t < 128) sbo[t] = __ldg(bo + t);
    __syncthreads();

    int R0 = blockIdx.x*128 + w*16;
    float c[16][4];
    #pragma unroll
    for (int i = 0; i < 16; i++){ c[i][0]=0.f; c[i][1]=0.f; c[i][2]=0.f; c[i][3]=0.f; }

    #pragma unroll
    for (int c8 = 0; c8 < 8; c8++){        // k chunks of 16
        uint32_t ah[4], al[4];
        size_t rA = (size_t)(R0 + g)*64 + c8*8 + u;
        size_t rB = (size_t)(R0 + g + 8)*64 + c8*8 + u;
        ah[0] = __ldg(g_cxhi + rA);     ah[1] = __ldg(g_cxhi + rB);
        ah[2] = __ldg(g_cxhi + rA + 4); ah[3] = __ldg(g_cxhi + rB + 4);
        al[0] = __ldg(g_cxlo + rA);     al[1] = __ldg(g_cxlo + rB);
        al[2] = __ldg(g_cxlo + rA + 4); al[3] = __ldg(g_cxlo + rB + 4);
        #pragma unroll
        for (int np = 0; np < 8; np++){    // 8 ldsm x4 -> 16 n-tiles
            uint32_t bh[4], bl[4];
            uint32_t rb = (uint32_t)((np*16 + ((l & 16) ? 8 : 0) + (l & 7))*ORS + ((l & 8) ? 16 : 0) + c8*32);
            ldsm_x4(bh, smb + rb);
            ldsm_x4(bl, smb + 128*ORS + rb);
            mma16816(c[2*np],   ah, bh);     mma16816(c[2*np+1], ah, bh+2);
            mma16816(c[2*np],   al, bh);     mma16816(c[2*np+1], al, bh+2);
            mma16816(c[2*np],   ah, bl);     mma16816(c[2*np+1], ah, bl+2);
        }
    }

    float* o0 = out + (size_t)(R0 + g)*EMB + u*2;
    float* o8 = out + (size_t)(R0 + g + 8)*EMB + u*2;
    #pragma unroll
    for (int nt = 0; nt < 16; nt++){
        int col = nt*8 + u*2;
        float2 a; a.x = c[nt][0] + sbo[col]; a.y = c[nt][1] + sbo[col+1];
        float2 b; b.x = c[nt][2] + sbo[col]; b.y = c[nt][3] + sbo[col+1];
        *(float2*)(o0 + nt*8) = a;
        *(float2*)(o8 + nt*8) = b;
    }
}

// ============================================================
extern "C" void kernel_launch(void* const* d_in, const int* in_sizes, int n_in,
                              void* d_out, int out_size)
{
    const float* values = (const float*)d_in[0];
    const float* keys   = (const float*)d_in[1];
    const float* query  = (const float*)d_in[2];
    const int*   mask   = (const int*)d_in[3];
    const float* Wv     = (const float*)d_in[4];
    const float* Wk     = (const float*)d_in[5];
    const float* Wq     = (const float*)d_in[6];
    const float* Wo     = (const float*)d_in[7];
    const float* bo     = (const float*)d_in[8];

    float* out  = (float*)d_out;
    float* attw = out + (size_t)N_B*S_LEN*EMB;   // tuple order: (out, attention_weights)

    cudaFuncSetAttribute(attn_kernel, cudaFuncAttributeMaxDynamicSharedMemorySize, SM_TOTAL);
    cudaFuncSetAttribute(out_kernel,  cudaFuncAttributeMaxDynamicSharedMemorySize, 2*128*ORS + 512);

    maskbits_kernel<<<(N_B*S_LEN*(S_LEN/32))/256, 256>>>(mask);
    woprep_kernel<<<EMB*EMB/256, 256>>>(Wo);
    proj_kernel<<<(N_B*S_LEN)/16, 256>>>(values, keys, query, Wv, Wk, Wq);
    attn_kernel<<<N_B*HEADS*(S_LEN/128), 256, SM_TOTAL>>>(attw);
    out_kernel<<<(N_B*S_LEN)/128, 256, 2*128*ORS + 512>>>(bo, out);
}